// round 1
// baseline (speedup 1.0000x reference)
#include <cuda_runtime.h>
#include <cuda_bf16.h>
#include <math.h>

// ---------------------------------------------------------------------------
// Problem dims (fixed by the dataset)
// ---------------------------------------------------------------------------
#define Bdim 2
#define Tdim 4096
#define Cdim 2048
#define HSZ  64
#define NHEAD (Cdim / HSZ)          // 32
#define Mrows (Bdim * Tdim)         // 8192
#define DW 128
#define DA 128
#define DV 64
#define DG 224

static const size_t BTC = (size_t)Bdim * Tdim * Cdim;   // 16,777,216

// ---------------------------------------------------------------------------
// Scratch (device globals — no allocations allowed)
// ---------------------------------------------------------------------------
__device__ float g_xr[Bdim * Tdim * Cdim];
__device__ float g_xw[Bdim * Tdim * Cdim];
__device__ float g_xk[Bdim * Tdim * Cdim];
__device__ float g_xv[Bdim * Tdim * Cdim];
__device__ float g_xa[Bdim * Tdim * Cdim];
__device__ float g_xg[Bdim * Tdim * Cdim];
__device__ float g_ko[Bdim * Tdim * Cdim];   // raw k gemm
__device__ float g_vg[Bdim * Tdim * Cdim];   // raw v gemm
__device__ float g_hw[Mrows * DW];
__device__ float g_ha[Mrows * DA];
__device__ float g_hv[Mrows * DV];
__device__ float g_hg[Mrows * DG];

// ---------------------------------------------------------------------------
// Kernel 1: time-shift + 6 mixes + v_first passthrough
// ---------------------------------------------------------------------------
__global__ __launch_bounds__(256) void mix_kernel(
    const float* __restrict__ x, const float* __restrict__ vf,
    const float* __restrict__ mr, const float* __restrict__ mw,
    const float* __restrict__ mk, const float* __restrict__ mv,
    const float* __restrict__ ma, const float* __restrict__ mg,
    float* __restrict__ out_vf)
{
    int idx = blockIdx.x * blockDim.x + threadIdx.x;
    if (idx >= (int)BTC) return;
    int c   = idx & (Cdim - 1);
    int row = idx >> 11;             // b*T + t
    int t   = row & (Tdim - 1);
    float xc = x[idx];
    float xp = (t == 0) ? 0.0f : x[idx - Cdim];
    float xx = xp - xc;
    g_xr[idx] = fmaf(xx, mr[c], xc);
    g_xw[idx] = fmaf(xx, mw[c], xc);
    g_xk[idx] = fmaf(xx, mk[c], xc);
    g_xv[idx] = fmaf(xx, mv[c], xc);
    g_xa[idx] = fmaf(xx, ma[c], xc);
    g_xg[idx] = fmaf(xx, mg[c], xc);
    out_vf[idx] = vf[idx];
}

// ---------------------------------------------------------------------------
// GEMM tiles
// ---------------------------------------------------------------------------
#define BM 128
#define BN 128
#define BK 16
#define TM 8
#define TN 8

// O[m,n] = sum_k A[m,k] * W[n,k]   (A: [M,K] row-major, W: [N,K] row-major)
// M % 128 == 0, N % 128 == 0, K % 16 == 0 (true for all call sites)
__global__ __launch_bounds__(256) void gemm_abT(
    const float* __restrict__ A, const float* __restrict__ W,
    float* __restrict__ O, int M, int N, int K)
{
    __shared__ float As[BK][BM];
    __shared__ float Bs[BK][BN];
    const int m0 = blockIdx.x * BM;
    const int n0 = blockIdx.y * BN;
    const int tid = threadIdx.x;
    const int lrow = tid >> 2;
    const int lk   = (tid & 3) * 4;
    const int tm = (tid >> 4) * TM;
    const int tn = (tid & 15) * TN;

    float acc[TM][TN] = {};
    for (int k0 = 0; k0 < K; k0 += BK) {
        #pragma unroll
        for (int p = 0; p < 2; p++) {
            int r = lrow + p * 64;
            float4 av = *(const float4*)&A[(size_t)(m0 + r) * K + k0 + lk];
            As[lk + 0][r] = av.x; As[lk + 1][r] = av.y;
            As[lk + 2][r] = av.z; As[lk + 3][r] = av.w;
            float4 bv = *(const float4*)&W[(size_t)(n0 + r) * K + k0 + lk];
            Bs[lk + 0][r] = bv.x; Bs[lk + 1][r] = bv.y;
            Bs[lk + 2][r] = bv.z; Bs[lk + 3][r] = bv.w;
        }
        __syncthreads();
        #pragma unroll
        for (int kk = 0; kk < BK; kk++) {
            float ra[TM], rb[TN];
            #pragma unroll
            for (int i = 0; i < TM; i += 4) *(float4*)&ra[i] = *(const float4*)&As[kk][tm + i];
            #pragma unroll
            for (int j = 0; j < TN; j += 4) *(float4*)&rb[j] = *(const float4*)&Bs[kk][tn + j];
            #pragma unroll
            for (int i = 0; i < TM; i++)
                #pragma unroll
                for (int j = 0; j < TN; j++)
                    acc[i][j] = fmaf(ra[i], rb[j], acc[i][j]);
        }
        __syncthreads();
    }
    #pragma unroll
    for (int i = 0; i < TM; i++) {
        float* orow = &O[(size_t)(m0 + tm + i) * N + n0 + tn];
        #pragma unroll
        for (int j = 0; j < TN; j += 4)
            *(float4*)&orow[j] = make_float4(acc[i][j], acc[i][j+1], acc[i][j+2], acc[i][j+3]);
    }
}

// Epilogue modes for gemm_ab
#define EPI_NONE 0
#define EPI_TANH 1
#define EPI_W    2
#define EPI_SIG  3
#define EPI_VMIX 4

__device__ __forceinline__ float sigmoidf_(float y) { return 1.0f / (1.0f + expf(-y)); }

// O[m,n] = epi( sum_k A[m,k] * B[k,n] )   (A: [M,K] row-major, B: [K,N] row-major)
// M % 128 == 0, K % 16 == 0, N % 32 == 0 (N may be < BN or not a multiple of BN)
template <int EPI>
__global__ __launch_bounds__(256) void gemm_ab(
    const float* __restrict__ A, const float* __restrict__ B,
    float* __restrict__ O, int M, int N, int K,
    const float* __restrict__ bias,
    const float* __restrict__ vg, const float* __restrict__ vf)
{
    __shared__ float As[BK][BM];
    __shared__ float Bs[BK][BN];
    const int m0 = blockIdx.x * BM;
    const int n0 = blockIdx.y * BN;
    const int tid = threadIdx.x;
    const int lrow = tid >> 2;
    const int lk   = (tid & 3) * 4;
    const int kr   = tid >> 5;          // 0..7
    const int nv   = (tid & 31) * 4;    // 0..124
    const int tm = (tid >> 4) * TM;
    const int tn = (tid & 15) * TN;

    float acc[TM][TN] = {};
    for (int k0 = 0; k0 < K; k0 += BK) {
        #pragma unroll
        for (int p = 0; p < 2; p++) {
            int r = lrow + p * 64;
            float4 av = *(const float4*)&A[(size_t)(m0 + r) * K + k0 + lk];
            As[lk + 0][r] = av.x; As[lk + 1][r] = av.y;
            As[lk + 2][r] = av.z; As[lk + 3][r] = av.w;
        }
        #pragma unroll
        for (int p = 0; p < 2; p++) {
            int krr = kr + p * 8;
            float4 bv = make_float4(0.f, 0.f, 0.f, 0.f);
            if (n0 + nv < N)   // N % 4 == 0 so float4 is all-in or all-out
                bv = *(const float4*)&B[(size_t)(k0 + krr) * N + n0 + nv];
            Bs[krr][nv + 0] = bv.x; Bs[krr][nv + 1] = bv.y;
            Bs[krr][nv + 2] = bv.z; Bs[krr][nv + 3] = bv.w;
        }
        __syncthreads();
        #pragma unroll
        for (int kk = 0; kk < BK; kk++) {
            float ra[TM], rb[TN];
            #pragma unroll
            for (int i = 0; i < TM; i += 4) *(float4*)&ra[i] = *(const float4*)&As[kk][tm + i];
            #pragma unroll
            for (int j = 0; j < TN; j += 4) *(float4*)&rb[j] = *(const float4*)&Bs[kk][tn + j];
            #pragma unroll
            for (int i = 0; i < TM; i++)
                #pragma unroll
                for (int j = 0; j < TN; j++)
                    acc[i][j] = fmaf(ra[i], rb[j], acc[i][j]);
        }
        __syncthreads();
    }

    #pragma unroll
    for (int i = 0; i < TM; i++) {
        int m = m0 + tm + i;
        #pragma unroll
        for (int j = 0; j < TN; j++) {
            int n = n0 + tn + j;
            if (n >= N) continue;
            float val = acc[i][j];
            float o;
            if (EPI == EPI_NONE) {
                o = val;
            } else if (EPI == EPI_TANH) {
                o = tanhf(val);
            } else if (EPI == EPI_W) {
                float y  = bias[n] + val;
                // softplus(-y) computed stably
                float sp = fmaxf(-y, 0.0f) + log1pf(expf(-fabsf(y)));
                o = -sp - 0.5f;
            } else if (EPI == EPI_SIG) {
                float y = val + (bias ? bias[n] : 0.0f);
                o = sigmoidf_(y);
            } else { // EPI_VMIX
                float s = sigmoidf_(bias[n] + val);
                size_t idx = (size_t)m * N + n;
                float vgv = vg[idx];
                o = vgv + (vf[idx] - vgv) * s;
            }
            O[(size_t)m * N + n] = o;
        }
    }
}

// ---------------------------------------------------------------------------
// Kernel: kk = headwise-normalize(k * k_k);  k_final = k * (1 + (a-1)*k_a)
// One warp per (row, head): 64 elements, 2 per lane.
// ---------------------------------------------------------------------------
__global__ __launch_bounds__(256) void kk_fin_kernel(
    const float* __restrict__ k_k, const float* __restrict__ k_a,
    const float* __restrict__ a_out,
    float* __restrict__ out_kk, float* __restrict__ out_k)
{
    int gw   = (blockIdx.x * blockDim.x + threadIdx.x) >> 5;
    int lane = threadIdx.x & 31;
    int row  = gw >> 5;           // 0..8191
    int h    = gw & 31;           // 0..31
    if (row >= Mrows) return;
    int base = row * Cdim + h * HSZ;
    int c0 = h * HSZ + lane, c1 = c0 + 32;

    float k0v = g_ko[base + lane];
    float k1v = g_ko[base + 32 + lane];
    float kk0 = k0v * k_k[c0];
    float kk1 = k1v * k_k[c1];
    float ss = kk0 * kk0 + kk1 * kk1;
    #pragma unroll
    for (int o = 16; o > 0; o >>= 1) ss += __shfl_xor_sync(0xFFFFFFFFu, ss, o);
    float inv = 1.0f / fmaxf(sqrtf(ss), 1e-12f);
    out_kk[base + lane]      = kk0 * inv;
    out_kk[base + 32 + lane] = kk1 * inv;

    float a0v = a_out[base + lane];
    float a1v = a_out[base + 32 + lane];
    out_k[base + lane]      = k0v * fmaf(a0v - 1.0f, k_a[c0], 1.0f);
    out_k[base + 32 + lane] = k1v * fmaf(a1v - 1.0f, k_a[c1], 1.0f);
}

// ---------------------------------------------------------------------------
// Launch
// ---------------------------------------------------------------------------
extern "C" void kernel_launch(void* const* d_in, const int* in_sizes, int n_in,
                              void* d_out, int out_size)
{
    const float* x   = (const float*)d_in[0];
    const float* vf  = (const float*)d_in[1];
    const float* x_r = (const float*)d_in[2];
    const float* x_w = (const float*)d_in[3];
    const float* x_k = (const float*)d_in[4];
    const float* x_v = (const float*)d_in[5];
    const float* x_a = (const float*)d_in[6];
    const float* x_g = (const float*)d_in[7];
    const float* w0  = (const float*)d_in[8];
    const float* w1  = (const float*)d_in[9];
    const float* w2  = (const float*)d_in[10];
    const float* a0  = (const float*)d_in[11];
    const float* a1  = (const float*)d_in[12];
    const float* a2  = (const float*)d_in[13];
    const float* v0  = (const float*)d_in[14];
    const float* v1  = (const float*)d_in[15];
    const float* v2  = (const float*)d_in[16];
    const float* g1  = (const float*)d_in[17];
    const float* g2  = (const float*)d_in[18];
    const float* k_k = (const float*)d_in[19];
    const float* k_a = (const float*)d_in[20];
    const float* Wr  = (const float*)d_in[21];
    const float* Wk  = (const float*)d_in[22];
    const float* Wv  = (const float*)d_in[23];
    (void)in_sizes; (void)n_in; (void)out_size;

    float* out = (float*)d_out;
    float* out_r  = out + 0 * BTC;
    float* out_w  = out + 1 * BTC;
    float* out_k  = out + 2 * BTC;
    float* out_v  = out + 3 * BTC;
    float* out_a  = out + 4 * BTC;
    float* out_g  = out + 5 * BTC;
    float* out_kk = out + 6 * BTC;
    float* out_vf = out + 7 * BTC;

    // scratch pointers
    float *p_xr, *p_xw, *p_xk, *p_xv, *p_xa, *p_xg, *p_ko, *p_vg, *p_hw, *p_ha, *p_hv, *p_hg;
    cudaGetSymbolAddress((void**)&p_xr, g_xr);
    cudaGetSymbolAddress((void**)&p_xw, g_xw);
    cudaGetSymbolAddress((void**)&p_xk, g_xk);
    cudaGetSymbolAddress((void**)&p_xv, g_xv);
    cudaGetSymbolAddress((void**)&p_xa, g_xa);
    cudaGetSymbolAddress((void**)&p_xg, g_xg);
    cudaGetSymbolAddress((void**)&p_ko, g_ko);
    cudaGetSymbolAddress((void**)&p_vg, g_vg);
    cudaGetSymbolAddress((void**)&p_hw, g_hw);
    cudaGetSymbolAddress((void**)&p_ha, g_ha);
    cudaGetSymbolAddress((void**)&p_hv, g_hv);
    cudaGetSymbolAddress((void**)&p_hg, g_hg);

    // 1. mixes + v_first copy
    mix_kernel<<<(int)((BTC + 255) / 256), 256>>>(x, vf, x_r, x_w, x_k, x_v, x_a, x_g, out_vf);

    dim3 gBig(Mrows / BM, Cdim / BN);   // (64, 16)

    // 2-4. big GEMMs (A @ W^T)
    gemm_abT<<<gBig, 256>>>(p_xr, Wr, out_r, Mrows, Cdim, Cdim);
    gemm_abT<<<gBig, 256>>>(p_xk, Wk, p_ko,  Mrows, Cdim, Cdim);
    gemm_abT<<<gBig, 256>>>(p_xv, Wv, p_vg,  Mrows, Cdim, Cdim);

    // 5-6. w path: hw = tanh(xw @ w1); w = -softplus(-(w0 + hw @ w2)) - 0.5
    gemm_ab<EPI_TANH><<<dim3(Mrows / BM, (DW + BN - 1) / BN), 256>>>(
        p_xw, w1, p_hw, Mrows, DW, Cdim, nullptr, nullptr, nullptr);
    gemm_ab<EPI_W><<<gBig, 256>>>(
        p_hw, w2, out_w, Mrows, Cdim, DW, w0, nullptr, nullptr);

    // 7-8. a path: ha = xa @ a1; a = sigmoid(a0 + ha @ a2)
    gemm_ab<EPI_NONE><<<dim3(Mrows / BM, (DA + BN - 1) / BN), 256>>>(
        p_xa, a1, p_ha, Mrows, DA, Cdim, nullptr, nullptr, nullptr);
    gemm_ab<EPI_SIG><<<gBig, 256>>>(
        p_ha, a2, out_a, Mrows, Cdim, DA, a0, nullptr, nullptr);

    // 9-10. v path: hv = xv @ v1; v = vg + (vf - vg) * sigmoid(v0 + hv @ v2)
    gemm_ab<EPI_NONE><<<dim3(Mrows / BM, (DV + BN - 1) / BN), 256>>>(
        p_xv, v1, p_hv, Mrows, DV, Cdim, nullptr, nullptr, nullptr);
    gemm_ab<EPI_VMIX><<<gBig, 256>>>(
        p_hv, v2, out_v, Mrows, Cdim, DV, v0, p_vg, vf);

    // 11-12. g path: hg = sigmoid(xg @ g1); g = hg @ g2
    gemm_ab<EPI_SIG><<<dim3(Mrows / BM, (DG + BN - 1) / BN), 256>>>(
        p_xg, g1, p_hg, Mrows, DG, Cdim, nullptr, nullptr, nullptr);
    gemm_ab<EPI_NONE><<<gBig, 256>>>(
        p_hg, g2, out_g, Mrows, Cdim, DG, nullptr, nullptr, nullptr);

    // 13. kk normalize + final k (needs a from step 8)
    int warps = Mrows * NHEAD;                 // 262144
    kk_fin_kernel<<<warps * 32 / 256, 256>>>(k_k, k_a, out_a, out_kk, out_k);
}